// round 11
// baseline (speedup 1.0000x reference)
#include <cuda_runtime.h>
#include <cuda_bf16.h>
#include <math.h>

#define Bc 32
#define Nc 64
#define Fc 1280
#define Hc 512
#define Ec 512
#define Vc 10000
#define Tc 80
#define SOSc 1
#define G4 2048
#define NBLK 148
#define TPB 512
#define NT79 79

typedef unsigned long long ull;

// ---------------- device scratch ----------------
__device__ float g_h[2][Bc * Hc];
__device__ float g_c[2][Bc * Hc];
__device__ float g_x[Bc * Ec];
__device__ float g_hq[Bc * Hc];        // full hq (bias included)
__device__ float g_glin[Bc * Fc];      // full glin (bias included)
__device__ float g_gh[Bc * G4];        // full gates h-part
__device__ float g_ctx[Bc * Fc];
__device__ float g_encproj[Bc * Nc * Hc];
__device__ float g_mean[Bc * Fc];
__device__ float g_gp[14][Bc * G4];    // gates x-part partials (K-split 14)
__device__ float g_pbv[NT79 * Bc];
__device__ int   g_pbi[NT79 * Bc];
__device__ unsigned g_bar;

#define HOFF ((size_t)Bc * Tc * Vc)
#define COFF (HOFF + (size_t)Bc * Hc)
#define AOFF (COFF + (size_t)Bc * Hc)

// dynamic smem carve (floats):
// sw 2x16384 | sb 2x4608 | sl 4096 | sred 512 | sredi 512 | aux 8
#define SW_BUF 16384
#define SB_BUF 4608
#define SMEM_FLOATS (2 * SW_BUF + 2 * SB_BUF + 4096 + 512 + 512 + 8)
#define SMEM_BYTES (SMEM_FLOATS * 4)

__device__ __forceinline__ float sigf(float x) { return 1.0f / (1.0f + expf(-x)); }

__device__ __forceinline__ ull pk2(float x) {
    ull r; asm("mov.b64 %0,{%1,%1};" : "=l"(r) : "r"(__float_as_uint(x))); return r;
}
__device__ __forceinline__ void fma2(ull& d, ull a, ull b) {
    asm("fma.rn.f32x2 %0,%1,%2,%0;" : "+l"(d) : "l"(a), "l"(b));
}
__device__ __forceinline__ ull add2(ull a, ull b) {
    ull d; asm("add.rn.f32x2 %0,%1,%2;" : "=l"(d) : "l"(a), "l"(b)); return d;
}
__device__ __forceinline__ float2 un2(ull v) {
    unsigned lo, hi; asm("mov.b64 {%0,%1},%2;" : "=r"(lo), "=r"(hi) : "l"(v));
    float2 f; f.x = __uint_as_float(lo); f.y = __uint_as_float(hi); return f;
}

__device__ __forceinline__ void cp16(void* smem, const void* gmem) {
    unsigned s = (unsigned)__cvta_generic_to_shared(smem);
    asm volatile("cp.async.cg.shared.global [%0], [%1], 16;" :: "r"(s), "l"(gmem));
}
#define CP_COMMIT() asm volatile("cp.async.commit_group;" ::: "memory")
template <int N> __device__ __forceinline__ void cp_wait() {
    asm volatile("cp.async.wait_group %0;" :: "n"(N) : "memory");
}

__device__ __forceinline__ void gridbar() {
    __syncthreads();
    if (threadIdx.x == 0) {
        __threadfence();
        unsigned t = atomicAdd(&g_bar, 1u) + 1u;
        unsigned target = ((t + NBLK - 1u) / NBLK) * NBLK;
        while (*((volatile unsigned*)&g_bar) < target) __nanosleep(32);
        __threadfence();
    }
    __syncthreads();
}

// ================= full-K (512) tile unit, double-buffered cp.async pipeline ======
// 4 K-planes (tid>>7); thread tile 4 cols x 8 batches. Weight chunks flow via
// cp.async into alternating buffers; chunk ch+1 is prefetched while ch computes.
template <bool LOGITS>
__device__ __forceinline__ void unit_fk(
    float* sw, float* sb, float* sl,
    const float* __restrict__ W, size_t ldw, int col0, int maxc,
    const float* __restrict__ hsrc, const float* __restrict__ bias,
    float* dstp, size_t dst_stride,
    float* __restrict__ dout, int t, int tile, int tid)
{
    const int ks = tid >> 7;            // plane 0..3
    const int lt = tid & 127;
    const int wrp = lt >> 5, lane = lt & 31;
    const int ct = wrp * 8 + (lane & 7);    // 0..31 col-thread
    const int bg = lane >> 3;               // 0..3 batch-group (8 batches)
    const int c4 = ct << 2, b8 = bg << 3;
    const int warp = tid >> 5, lane2 = tid & 31;
    const int maxc4 = maxc - 4;
    ull A[16];
#pragma unroll
    for (int i = 0; i < 16; i++) A[i] = 0;

    // prologue: stage chunk 0 into buf 0
    {
        float* swb = sw; float* sbb = sb;
#pragma unroll
        for (int e = tid; e < 4096; e += TPB) {
            int kk = e >> 5, cc = (e & 31) << 2;
            int cg = col0 + cc; if (cg > maxc4) cg = maxc4;
            cp16(&swb[kk * 128 + cc], &W[(size_t)kk * ldw + cg]);
        }
#pragma unroll
        for (int idx = warp; idx < 128; idx += 16) {
            int b = idx & 31, kkc = (idx >> 5) << 5;
            sbb[(kkc + lane2) * 36 + b] = __ldcg(&hsrc[b * Hc + kkc + lane2]);
        }
        CP_COMMIT();
    }
#pragma unroll
    for (int ch = 0; ch < 4; ch++) {
        if (ch < 3) {
            // prefetch chunk ch+1 into the other buffer
            int kc = (ch + 1) * 128;
            float* swb = sw + ((ch + 1) & 1) * SW_BUF;
            float* sbb = sb + ((ch + 1) & 1) * SB_BUF;
#pragma unroll
            for (int e = tid; e < 4096; e += TPB) {
                int kk = e >> 5, cc = (e & 31) << 2;
                int cg = col0 + cc; if (cg > maxc4) cg = maxc4;
                cp16(&swb[kk * 128 + cc], &W[(size_t)(kc + kk) * ldw + cg]);
            }
#pragma unroll
            for (int idx = warp; idx < 128; idx += 16) {
                int b = idx & 31, kkc = (idx >> 5) << 5;
                sbb[(kkc + lane2) * 36 + b] = __ldcg(&hsrc[b * Hc + kc + kkc + lane2]);
            }
            CP_COMMIT();
            cp_wait<1>();      // chunk ch's copies done; ch+1 may be in flight
        } else {
            cp_wait<0>();
        }
        __syncthreads();
        {
            const float* swp = sw + (ch & 1) * SW_BUF + (ks * 32) * 128 + c4;
            const float* sbp = sb + (ch & 1) * SB_BUF + (ks * 32) * 36 + b8;
#pragma unroll 8
            for (int kk = 0; kk < 32; kk++) {
                float4 w = *(const float4*)(swp + kk * 128);
                ulonglong2 b01 = *(const ulonglong2*)(sbp + kk * 36);
                ulonglong2 b23 = *(const ulonglong2*)(sbp + kk * 36 + 4);
                ull w0 = pk2(w.x), w1 = pk2(w.y), w2 = pk2(w.z), w3 = pk2(w.w);
                fma2(A[0],  w0, b01.x); fma2(A[1],  w1, b01.x);
                fma2(A[2],  w2, b01.x); fma2(A[3],  w3, b01.x);
                fma2(A[4],  w0, b01.y); fma2(A[5],  w1, b01.y);
                fma2(A[6],  w2, b01.y); fma2(A[7],  w3, b01.y);
                fma2(A[8],  w0, b23.x); fma2(A[9],  w1, b23.x);
                fma2(A[10], w2, b23.x); fma2(A[11], w3, b23.x);
                fma2(A[12], w0, b23.y); fma2(A[13], w1, b23.y);
                fma2(A[14], w2, b23.y); fma2(A[15], w3, b23.y);
            }
        }
        __syncthreads();   // protects buffer reuse at next prefetch
    }
    // plane reduce (red lives in sw buf0; last compute read buf1)
    ull* red = (ull*)sw;
    if (ks > 0) {
#pragma unroll
        for (int i = 0; i < 16; i++) red[((ks - 1) * 128 + lt) * 16 + i] = A[i];
    }
    __syncthreads();
    if (ks == 0) {
#pragma unroll
        for (int p = 0; p < 3; p++)
#pragma unroll
            for (int i = 0; i < 16; i++)
                A[i] = add2(A[i], red[(p * 128 + lt) * 16 + i]);
        float vals[8][4];
#pragma unroll
        for (int bp = 0; bp < 4; bp++)
#pragma unroll
            for (int c = 0; c < 4; c++) {
                float2 q = un2(A[bp * 4 + c]);
                vals[bp * 2 + 0][c] = q.x;
                vals[bp * 2 + 1][c] = q.y;
            }
        if (!LOGITS) {
            float4 bb = make_float4(0.f, 0.f, 0.f, 0.f);
            if (bias) bb = *(const float4*)&bias[c4];
#pragma unroll
            for (int i = 0; i < 8; i++) {
                int b = b8 + i;
                *(float4*)&dstp[(size_t)b * dst_stride + c4] =
                    make_float4(vals[i][0] + bb.x, vals[i][1] + bb.y,
                                vals[i][2] + bb.z, vals[i][3] + bb.w);
            }
        } else {
#pragma unroll
            for (int i = 0; i < 8; i++) {
                int b = b8 + i;
#pragma unroll
                for (int c = 0; c < 4; c++) {
                    int col = col0 + c4 + c;
                    float v = -INFINITY;
                    if (col < Vc) {
                        v = vals[i][c] + bias[c4 + c];
                        dout[(size_t)b * Tc * Vc + (size_t)t * Vc + col] = v;
                    }
                    sl[b * 128 + c4 + c] = v;
                }
            }
        }
    }
    if (LOGITS) {
        __syncthreads();
        if (tid < 32) {
            int b = tid;
            float bv = -INFINITY; int bi = 0;
#pragma unroll 8
            for (int cq = 0; cq < 128; cq++) {
                float v = sl[b * 128 + cq];
                if (v > bv) { bv = v; bi = col0 + cq; }
            }
            g_pbv[tile * 32 + b] = bv;
            g_pbi[tile * 32 + b] = bi;
        }
    }
}

// ================= K-chunk partial unit (gates x-part) =================
template <int NKK>
__device__ __forceinline__ void unit_gemm(
    float* sw, float* sb,
    const float* __restrict__ W, size_t ldw, int kc, int col0,
    float* dstp, size_t dst_stride, int tid)
{
#pragma unroll
    for (int e = tid; e < NKK * 32; e += TPB) {
        int kk = e >> 5, cc = (e & 31) << 2;
        cp16(&sw[kk * 128 + cc], &W[(size_t)(kc + kk) * ldw + col0 + cc]);
    }
    {
        int warp = tid >> 5, lane = tid & 31;
#pragma unroll
        for (int idx = warp; idx < NKK; idx += 16) {
            int b = idx & 31, kkc = (idx >> 5) << 5;
            int k = kc + kkc + lane;
            float v = (k < Ec) ? __ldcg(&g_x[b * Ec + k])
                               : __ldcg(&g_ctx[b * Fc + (k - Ec)]);
            sb[(kkc + lane) * 36 + b] = v;
        }
    }
    CP_COMMIT();
    cp_wait<0>();
    __syncthreads();
    const int ks = tid >> 8;
    const int lt = tid & 255;
    const int wrp = lt >> 5, lane = lt & 31;
    const int ct = (wrp & 3) * 8 + (lane & 7);
    const int bg = (wrp >> 2) * 4 + (lane >> 3);
    const int c4 = ct << 2, b4 = bg << 2;
    ull a0 = 0, a1 = 0, a2 = 0, a3 = 0, a4 = 0, a5 = 0, a6 = 0, a7 = 0;
    {
        const float* swp = sw + ks * (NKK / 2) * 128 + c4;
        const float* sbp = sb + ks * (NKK / 2) * 36 + b4;
#pragma unroll 8
        for (int kk = 0; kk < NKK / 2; kk++) {
            ulonglong2 w = *(const ulonglong2*)(swp + kk * 128);
            float4 bb = *(const float4*)(sbp + kk * 36);
            ull p0 = pk2(bb.x), p1 = pk2(bb.y), p2 = pk2(bb.z), p3 = pk2(bb.w);
            fma2(a0, w.x, p0); fma2(a1, w.y, p0);
            fma2(a2, w.x, p1); fma2(a3, w.y, p1);
            fma2(a4, w.x, p2); fma2(a5, w.y, p2);
            fma2(a6, w.x, p3); fma2(a7, w.y, p3);
        }
    }
    __syncthreads();
    ull* red = (ull*)sw;
    if (ks == 1) {
        red[lt * 8 + 0] = a0; red[lt * 8 + 1] = a1;
        red[lt * 8 + 2] = a2; red[lt * 8 + 3] = a3;
        red[lt * 8 + 4] = a4; red[lt * 8 + 5] = a5;
        red[lt * 8 + 6] = a6; red[lt * 8 + 7] = a7;
    }
    __syncthreads();
    if (ks == 0) {
        a0 = add2(a0, red[lt * 8 + 0]); a1 = add2(a1, red[lt * 8 + 1]);
        a2 = add2(a2, red[lt * 8 + 2]); a3 = add2(a3, red[lt * 8 + 3]);
        a4 = add2(a4, red[lt * 8 + 4]); a5 = add2(a5, red[lt * 8 + 5]);
        a6 = add2(a6, red[lt * 8 + 6]); a7 = add2(a7, red[lt * 8 + 7]);
        float2 q0, q1;
        q0 = un2(a0); q1 = un2(a1);
        *(float4*)&dstp[(size_t)(b4 + 0) * dst_stride + c4] = make_float4(q0.x, q0.y, q1.x, q1.y);
        q0 = un2(a2); q1 = un2(a3);
        *(float4*)&dstp[(size_t)(b4 + 1) * dst_stride + c4] = make_float4(q0.x, q0.y, q1.x, q1.y);
        q0 = un2(a4); q1 = un2(a5);
        *(float4*)&dstp[(size_t)(b4 + 2) * dst_stride + c4] = make_float4(q0.x, q0.y, q1.x, q1.y);
        q0 = un2(a6); q1 = un2(a7);
        *(float4*)&dstp[(size_t)(b4 + 3) * dst_stride + c4] = make_float4(q0.x, q0.y, q1.x, q1.y);
    }
    __syncthreads();
}

// ---------------- init kernels ----------------
__global__ void k_mean(const float* __restrict__ feat, const float* __restrict__ emb) {
    int idx = blockIdx.x * blockDim.x + threadIdx.x;
    if (idx == 0) g_bar = 0u;
    if (idx < Bc * Ec) g_x[idx] = emb[(size_t)SOSc * Ec + (idx % Ec)];
    if (idx >= Bc * Fc) return;
    int b = idx / Fc, f = idx % Fc;
    float s = 0.f;
    const float* p = feat + (size_t)b * Nc * Fc + f;
#pragma unroll 8
    for (int n = 0; n < Nc; n++) s += p[(size_t)n * Fc];
    g_mean[idx] = s * (1.0f / 64.0f);
}

__global__ void k_h0c0(const float* __restrict__ Wh, const float* __restrict__ bh,
                       const float* __restrict__ Wc, const float* __restrict__ bc) {
    __shared__ __align__(16) float sm[64 * 36];
    int tid = threadIdx.x;
    int colg = blockIdx.x * 64 + (tid & 63);
    int bgrp = tid >> 6;
    float acc[8] = {0, 0, 0, 0, 0, 0, 0, 0};
    const float* W; float bias; float* dst;
    if (colg < Hc) { W = Wh + colg; bias = bh[colg]; dst = g_h[0] + colg; }
    else { W = Wc + (colg - Hc); bias = bc[colg - Hc]; dst = g_c[0] + (colg - Hc); }
    for (int kc = 0; kc < Fc; kc += 64) {
        __syncthreads();
        for (int e = tid; e < 2048; e += 256) {
            int kk = e >> 5, b = e & 31;
            sm[kk * 36 + b] = g_mean[b * Fc + kc + kk];
        }
        __syncthreads();
#pragma unroll 8
        for (int kk = 0; kk < 64; kk++) {
            float w = W[(size_t)(kc + kk) * Hc];
            const float* xr = &sm[kk * 36 + bgrp * 8];
#pragma unroll
            for (int i = 0; i < 8; i++) acc[i] = fmaf(xr[i], w, acc[i]);
        }
    }
#pragma unroll
    for (int i = 0; i < 8; i++) dst[(bgrp * 8 + i) * Hc] = acc[i] + bias;
}

__global__ void k_encproj(const float* __restrict__ feat, const float* __restrict__ W2,
                          const float* __restrict__ b2) {
    int tid = threadIdx.x;
    int rowbase = blockIdx.x * 64;
    int colbase = blockIdx.y * 64;
    int col = colbase + (tid & 63);
    int rgrp = tid >> 6;
    float acc[16];
#pragma unroll
    for (int i = 0; i < 16; i++) acc[i] = 0.f;
    __shared__ float As[64][33];
    __shared__ float Ws[32][65];
    for (int kc = 0; kc < Fc; kc += 32) {
        for (int e = tid; e < 64 * 32; e += 256) {
            int r = e >> 5, kk = e & 31;
            As[r][kk] = feat[(size_t)(rowbase + r) * Fc + kc + kk];
        }
        for (int e = tid; e < 32 * 64; e += 256) {
            int kk = e >> 6, c = e & 63;
            Ws[kk][c] = W2[(size_t)(kc + kk) * Hc + colbase + c];
        }
        __syncthreads();
#pragma unroll 8
        for (int kk = 0; kk < 32; kk++) {
            float w = Ws[kk][tid & 63];
#pragma unroll
            for (int i = 0; i < 16; i++) acc[i] += As[rgrp * 16 + i][kk] * w;
        }
        __syncthreads();
    }
    float bb = b2[col];
#pragma unroll
    for (int i = 0; i < 16; i++)
        g_encproj[(size_t)(rowbase + rgrp * 16 + i) * Hc + col] = acc[i] + bb;
}

// ---------------- persistent kernel ----------------
__global__ void __launch_bounds__(TPB, 1) k_persist(
    const float* __restrict__ feat, const float* __restrict__ emb,
    const float* __restrict__ W1, const float* __restrict__ b1,
    const float* __restrict__ Va, const float* __restrict__ bVa,
    const float* __restrict__ Wg, const float* __restrict__ bg,
    const float* __restrict__ Wx, const float* __restrict__ Whh,
    const float* __restrict__ blstm, const float* __restrict__ Wout,
    const float* __restrict__ bout, float* __restrict__ dout)
{
    extern __shared__ __align__(16) float dsm[];
    float* sw   = dsm;                            // 2x16384
    float* sb   = dsm + 2 * SW_BUF;               // 2x4608
    float* sl   = sb + 2 * SB_BUF;                // 4096
    float* sred = sl + 4096;                      // 512
    int*  sredi = (int*)(sred + 512);             // 512
    float* s_aux = (float*)(sredi + 512);         // 8

    const int bid = blockIdx.x;
    const int tid = threadIdx.x;

    // ===== pre-loop: hq(0)/glin(0)/gates-h(0) from h(0) =====
    if (bid < 30) {
        int u = bid;
        if (u < 4) {
            int col0 = u * 128;
            unit_fk<false>(sw, sb, sl, W1, Hc, col0, Hc, g_h[0], b1 + col0,
                           g_hq + col0, Hc, nullptr, 0, 0, tid);
        } else if (u < 14) {
            int col0 = (u - 4) * 128;
            unit_fk<false>(sw, sb, sl, Wg, Fc, col0, Fc, g_h[0], bg + col0,
                           g_glin + col0, Fc, nullptr, 0, 0, tid);
        } else {
            int col0 = (u - 14) * 128;
            unit_fk<false>(sw, sb, sl, Whh, G4, col0, G4, g_h[0], nullptr,
                           g_gh + col0, G4, nullptr, 0, 0, tid);
        }
    }
    gridbar();

    for (int t = 0; t < Tc; t++) {
        const int rp = t & 1, wp = rp ^ 1;

        // ===== PHASE A: attention (0..127) || argmax(t-1)->x (128..147) =====
        if (bid < 128) {
            int b = bid >> 2, sub = bid & 3;
            sl[tid] = __ldcg(&g_hq[b * Hc + tid]);   // Hc == TPB, bias included
            __syncthreads();
            int warp = tid >> 5, lane = tid & 31;
#pragma unroll
            for (int ni = 0; ni < 4; ni++) {
                int n = warp + ni * 16;
                const float* ep = g_encproj + (size_t)(b * Nc + n) * Hc;
                float acc = 0.f;
#pragma unroll 4
                for (int k = lane; k < Hc; k += 32) {
                    float v = sl[k] + ep[k];
                    acc = fmaf(fmaxf(v, 0.f), Va[k], acc);
                }
#pragma unroll
                for (int o = 16; o; o >>= 1) acc += __shfl_down_sync(0xffffffffu, acc, o);
                if (lane == 0) sred[n] = acc + bVa[0];
            }
            __syncthreads();
            if (tid < 64) {
                float m = sred[tid];
#pragma unroll
                for (int o = 16; o; o >>= 1) m = fmaxf(m, __shfl_xor_sync(0xffffffffu, m, o));
                if (lane == 0) s_aux[tid >> 5] = m;
            }
            __syncthreads();
            if (tid < 64) {
                float M = fmaxf(s_aux[0], s_aux[1]);
                float e = expf(sred[tid] - M);
                sred[tid] = e;
                float ss = e;
#pragma unroll
                for (int o = 16; o; o >>= 1) ss += __shfl_xor_sync(0xffffffffu, ss, o);
                if (lane == 0) s_aux[2 + (tid >> 5)] = ss;
            }
            __syncthreads();
            if (tid < 64) {
                float wv = sred[tid] / (s_aux[2] + s_aux[3]);
                sred[tid] = wv;
                if (sub == 0)
                    dout[AOFF + (size_t)b * Tc * Nc + (size_t)t * Nc + tid] = wv;
            }
            __syncthreads();
            if (tid < 320) {
                int f = sub * 320 + tid;
                const float* fb = feat + (size_t)b * Nc * Fc + f;
                float acc = 0.f;
#pragma unroll 8
                for (int n = 0; n < 64; n++) acc = fmaf(fb[(size_t)n * Fc], sred[n], acc);
                float gl = __ldcg(&g_glin[b * Fc + f]);
                g_ctx[b * Fc + f] = acc * sigf(gl);
            }
        } else if (t > 0) {
            int i = bid - 128;
            int half = tid >> 8, lt2 = tid & 255;
            int b = (i < 12) ? (2 * i + half) : (24 + (i - 12));
            bool active = (i < 12) || (half == 0);
            float bv = -INFINITY; int bi2 = 0x7fffffff;
            if (active && lt2 < NT79) {
                bv = __ldcg(&g_pbv[lt2 * 32 + b]);
                bi2 = __ldcg(&g_pbi[lt2 * 32 + b]);
            }
            sred[tid] = bv; sredi[tid] = bi2;
            __syncthreads();
            for (int o = 128; o; o >>= 1) {
                if (lt2 < o) {
                    if (sred[tid + o] > sred[tid] ||
                        (sred[tid + o] == sred[tid] && sredi[tid + o] < sredi[tid])) {
                        sred[tid] = sred[tid + o];
                        sredi[tid] = sredi[tid + o];
                    }
                }
                __syncthreads();
            }
            if (active) {
                int best = sredi[half * 256];
                for (int e = lt2; e < Ec; e += 256)
                    g_x[b * Ec + e] = emb[(size_t)best * Ec + e];
            }
        }
        gridbar();

        // ===== PHASE C: gates x/ctx part: 16 tiles x 14 K-chunks(128) = 224 units =====
        for (int u = bid; u < 224; u += NBLK) {
            int tile = u / 14, kch = u % 14;
            unit_gemm<128>(sw, sb, Wx, G4, kch * 128, tile * 128,
                           g_gp[kch] + tile * 128, G4, tid);
        }
        gridbar();

        // ===== PHASE D: LSTM pointwise (g_gh + 14 partials) =====
        if (bid < 32) {
            int id = bid * TPB + tid;
            int b = id >> 9, j = id & 511;
            float gi = blstm[j]          + __ldcg(&g_gh[(size_t)b * G4 + j]);
            float gf = blstm[Hc + j]     + __ldcg(&g_gh[(size_t)b * G4 + Hc + j]);
            float gg = blstm[2 * Hc + j] + __ldcg(&g_gh[(size_t)b * G4 + 2 * Hc + j]);
            float go = blstm[3 * Hc + j] + __ldcg(&g_gh[(size_t)b * G4 + 3 * Hc + j]);
#pragma unroll
            for (int p = 0; p < 14; p++) {
                const float* gp = g_gp[p] + (size_t)b * G4;
                gi += __ldcg(&gp[j]);
                gf += __ldcg(&gp[Hc + j]);
                gg += __ldcg(&gp[2 * Hc + j]);
                go += __ldcg(&gp[3 * Hc + j]);
            }
            float cprev = g_c[rp][b * Hc + j];
            float iv = sigf(gi), fv = sigf(gf), gv = tanhf(gg), ov = sigf(go);
            float c2 = fv * cprev + iv * gv;
            float h2 = ov * tanhf(c2);
            g_c[wp][b * Hc + j] = c2;
            g_h[wp][b * Hc + j] = h2;
            if (t == Tc - 1) {
                dout[HOFF + b * Hc + j] = h2;
                dout[COFF + b * Hc + j] = c2;
            }
        }
        gridbar();

        // ===== PHASE E: logits(t) [79 tiles] || hq/glin/gates-h(t+1) [30 units] =====
        if (bid < NT79) {
            unit_fk<true>(sw, sb, sl, Wout, Vc, bid * 128, Vc, g_h[wp],
                          bout + bid * 128, nullptr, 0, dout, t, bid, tid);
        } else if (bid < 109) {
            int u = bid - NT79;
            if (u < 4) {
                int col0 = u * 128;
                unit_fk<false>(sw, sb, sl, W1, Hc, col0, Hc, g_h[wp], b1 + col0,
                               g_hq + col0, Hc, nullptr, 0, 0, tid);
            } else if (u < 14) {
                int col0 = (u - 4) * 128;
                unit_fk<false>(sw, sb, sl, Wg, Fc, col0, Fc, g_h[wp], bg + col0,
                               g_glin + col0, Fc, nullptr, 0, 0, tid);
            } else {
                int col0 = (u - 14) * 128;
                unit_fk<false>(sw, sb, sl, Whh, G4, col0, G4, g_h[wp], nullptr,
                               g_gh + col0, G4, nullptr, 0, 0, tid);
            }
        }
        gridbar();
    }
}

// ---------------- launcher ----------------
extern "C" void kernel_launch(void* const* d_in, const int* in_sizes, int n_in,
                              void* d_out, int out_size) {
    int off = (n_in > 2 && in_sizes[2] == 1) ? 1 : 0;
    const float* feat  = (const float*)d_in[0];
    const float* emb   = (const float*)d_in[2 + off];
    const float* W1    = (const float*)d_in[3 + off];
    const float* b1    = (const float*)d_in[4 + off];
    const float* W2    = (const float*)d_in[5 + off];
    const float* b2    = (const float*)d_in[6 + off];
    const float* Va    = (const float*)d_in[7 + off];
    const float* bVa   = (const float*)d_in[8 + off];
    const float* Wh    = (const float*)d_in[9 + off];
    const float* bh    = (const float*)d_in[10 + off];
    const float* Wc    = (const float*)d_in[11 + off];
    const float* bc    = (const float*)d_in[12 + off];
    const float* Wg    = (const float*)d_in[13 + off];
    const float* bg    = (const float*)d_in[14 + off];
    const float* Wx    = (const float*)d_in[15 + off];
    const float* Whh   = (const float*)d_in[16 + off];
    const float* blstm = (const float*)d_in[17 + off];
    const float* Wout  = (const float*)d_in[18 + off];
    const float* bout  = (const float*)d_in[19 + off];
    float* out = (float*)d_out;

    cudaFuncSetAttribute(k_persist, cudaFuncAttributeMaxDynamicSharedMemorySize, SMEM_BYTES);

    k_mean<<<160, 256>>>(feat, emb);
    k_h0c0<<<16, 256>>>(Wh, bh, Wc, bc);
    k_encproj<<<dim3(32, 8), 256>>>(feat, W2, b2);
    k_persist<<<NBLK, TPB, SMEM_BYTES>>>(feat, emb, W1, b1, Va, bVa, Wg, bg,
                                         Wx, Whh, blstm, Wout, bout, out);
}

// round 13
// speedup vs baseline: 1.0078x; 1.0078x over previous
#include <cuda_runtime.h>
#include <cuda_bf16.h>
#include <math.h>

#define Bc 32
#define Nc 64
#define Fc 1280
#define Hc 512
#define Ec 512
#define Vc 10000
#define Tc 80
#define SOSc 1
#define G4 2048
#define NBLK 148
#define TPB 1024
#define NT79 79

typedef unsigned long long ull;

// ---------------- device scratch ----------------
__device__ float g_h[2][Bc * Hc];
__device__ float g_c[2][Bc * Hc];
__device__ float g_x[Bc * Ec];
__device__ float g_hq[Bc * Hc];        // full hq (bias included)
__device__ float g_glin[Bc * Fc];      // full glin (bias included)
__device__ float g_gh[Bc * G4];        // full gates h-part
__device__ float g_ctx[Bc * Fc];
__device__ float g_encproj[Bc * Nc * Hc];
__device__ float g_mean[Bc * Fc];
__device__ float g_gp[14][Bc * G4];    // gates x-part partials (K-split 14)
__device__ float g_pbv[NT79 * Bc];
__device__ int   g_pbi[NT79 * Bc];
__device__ unsigned g_bar;

#define HOFF ((size_t)Bc * Tc * Vc)
#define COFF (HOFF + (size_t)Bc * Hc)
#define AOFF (COFF + (size_t)Bc * Hc)

// dynamic smem carve (floats): sw 16384 | sb 4608 | sl 4096 | sred 1024 | sredi 1024 | aux 8
#define SMEM_FLOATS (16384 + 4608 + 4096 + 1024 + 1024 + 8)
#define SMEM_BYTES (SMEM_FLOATS * 4)

__device__ __forceinline__ float sigf(float x) { return 1.0f / (1.0f + expf(-x)); }

__device__ __forceinline__ ull pk2(float x) {
    ull r; asm("mov.b64 %0,{%1,%1};" : "=l"(r) : "r"(__float_as_uint(x))); return r;
}
__device__ __forceinline__ void fma2(ull& d, ull a, ull b) {
    asm("fma.rn.f32x2 %0,%1,%2,%0;" : "+l"(d) : "l"(a), "l"(b));
}
__device__ __forceinline__ ull add2(ull a, ull b) {
    ull d; asm("add.rn.f32x2 %0,%1,%2;" : "=l"(d) : "l"(a), "l"(b)); return d;
}
__device__ __forceinline__ float2 un2(ull v) {
    unsigned lo, hi; asm("mov.b64 {%0,%1},%2;" : "=r"(lo), "=r"(hi) : "l"(v));
    float2 f; f.x = __uint_as_float(lo); f.y = __uint_as_float(hi); return f;
}

__device__ __forceinline__ void gridbar() {
    __syncthreads();
    if (threadIdx.x == 0) {
        __threadfence();
        unsigned t = atomicAdd(&g_bar, 1u) + 1u;
        unsigned target = ((t + NBLK - 1u) / NBLK) * NBLK;
        while (*((volatile unsigned*)&g_bar) < target) __nanosleep(32);
        __threadfence();
    }
    __syncthreads();
}

// ================= unified SMEM-tile GEMM unit (TPB=1024) =================
// C[32 x 128cols] over NCH chunks of 128 k. 4 K-planes (tid>>8) x 256 threads.
// Thread tile: 4 cols x 4 batches (8 ull accumulators).
// Warp lane map: ct = (wrp&3)*8+(lane&7)  -> weight LDS.128 spans 128B (1 phase)
//                bg = (wrp>>2)*4+(lane>>3)-> operand LDS.128 spans 64B (1 phase)
// SRCMODE 0: operand hsrc[b*Hc + k]; SRCMODE 1: x/ctx concat at global k.
// NOTE: trailing __syncthreads() before return is LOAD-BEARING — the plane
// partials live in sw, which the next unit's weight staging overwrites.
template <int NCH, int SRCMODE, bool LOGITS>
__device__ __forceinline__ void unit_g(
    float* sw, float* sb, float* sl,
    const float* __restrict__ W, size_t ldw, int kbase, int col0, int maxc,
    const float* __restrict__ hsrc, const float* __restrict__ bias,
    float* dstp, size_t dst_stride,
    float* __restrict__ dout, int t, int tile, int tid)
{
    const int ks = tid >> 8;                 // plane 0..3
    const int lt = tid & 255;
    const int wrp = lt >> 5, lane = lt & 31;
    const int ct = (wrp & 3) * 8 + (lane & 7);
    const int bg = (wrp >> 2) * 4 + (lane >> 3);
    const int c4 = ct << 2, b4 = bg << 2;
    const int warp32 = tid >> 5, lane2 = tid & 31;
    const int maxc4 = maxc - 4;
    ull A[8];
#pragma unroll
    for (int i = 0; i < 8; i++) A[i] = 0;

#pragma unroll
    for (int ch = 0; ch < NCH; ch++) {
        const int kc = kbase + ch * 128;
        // stage weights: 128 rows x 128 cols
#pragma unroll
        for (int e = tid; e < 4096; e += TPB) {
            int kk = e >> 5, cc = (e & 31) << 2;
            int cg = col0 + cc; if (cg > maxc4) cg = maxc4;
            *(float4*)&sw[kk * 128 + cc] = *(const float4*)&W[(size_t)(kc + kk) * ldw + cg];
        }
        // stage operand transposed: sb[k*36 + b]
#pragma unroll
        for (int idx = warp32; idx < 128; idx += 32) {
            int b = idx & 31, kkc = (idx >> 5) << 5;
            int k = kc + kkc + lane2;
            float v;
            if (SRCMODE == 0) v = __ldcg(&hsrc[b * Hc + k]);
            else v = (k < Ec) ? __ldcg(&g_x[b * Ec + k])
                              : __ldcg(&g_ctx[b * Fc + (k - Ec)]);
            sb[(kkc + lane2) * 36 + b] = v;
        }
        __syncthreads();
        {
            const float* swp = sw + (ks * 32) * 128 + c4;
            const float* sbp = sb + (ks * 32) * 36 + b4;
#pragma unroll 8
            for (int kk = 0; kk < 32; kk++) {
                float4 w = *(const float4*)(swp + kk * 128);
                ulonglong2 bb = *(const ulonglong2*)(sbp + kk * 36);
                ull w0 = pk2(w.x), w1 = pk2(w.y), w2 = pk2(w.z), w3 = pk2(w.w);
                fma2(A[0], w0, bb.x); fma2(A[1], w1, bb.x);
                fma2(A[2], w2, bb.x); fma2(A[3], w3, bb.x);
                fma2(A[4], w0, bb.y); fma2(A[5], w1, bb.y);
                fma2(A[6], w2, bb.y); fma2(A[7], w3, bb.y);
            }
        }
        __syncthreads();
    }
    // plane reduce through sw (weights no longer needed)
    ull* red = (ull*)sw;
    if (ks > 0) {
#pragma unroll
        for (int i = 0; i < 8; i++) red[((ks - 1) * 256 + lt) * 8 + i] = A[i];
    }
    __syncthreads();
    if (ks == 0) {
#pragma unroll
        for (int p = 0; p < 3; p++)
#pragma unroll
            for (int i = 0; i < 8; i++)
                A[i] = add2(A[i], red[(p * 256 + lt) * 8 + i]);
        // unpack: A[c] = (b4, b4+1) col c ; A[4+c] = (b4+2, b4+3) col c
        float vals[4][4];
#pragma unroll
        for (int c = 0; c < 4; c++) {
            float2 q0 = un2(A[c]), q1 = un2(A[4 + c]);
            vals[0][c] = q0.x; vals[1][c] = q0.y;
            vals[2][c] = q1.x; vals[3][c] = q1.y;
        }
        if (!LOGITS) {
            float4 bb = make_float4(0.f, 0.f, 0.f, 0.f);
            if (bias) bb = *(const float4*)&bias[c4];
#pragma unroll
            for (int i = 0; i < 4; i++) {
                int b = b4 + i;
                *(float4*)&dstp[(size_t)b * dst_stride + c4] =
                    make_float4(vals[i][0] + bb.x, vals[i][1] + bb.y,
                                vals[i][2] + bb.z, vals[i][3] + bb.w);
            }
        } else {
#pragma unroll
            for (int i = 0; i < 4; i++) {
                int b = b4 + i;
#pragma unroll
                for (int c = 0; c < 4; c++) {
                    int col = col0 + c4 + c;
                    float v = -INFINITY;
                    if (col < Vc) {
                        v = vals[i][c] + bias[c4 + c];
                        dout[(size_t)b * Tc * Vc + (size_t)t * Vc + col] = v;
                    }
                    sl[b * 128 + c4 + c] = v;
                }
            }
        }
    }
    if (LOGITS) {
        __syncthreads();
        if (tid < 32) {
            int b = tid;
            float bv = -INFINITY; int bi = 0;
#pragma unroll 8
            for (int cq = 0; cq < 128; cq++) {
                float v = sl[b * 128 + cq];
                if (v > bv) { bv = v; bi = col0 + cq; }
            }
            g_pbv[tile * 32 + b] = bv;
            g_pbi[tile * 32 + b] = bi;
        }
    }
    __syncthreads();   // protect sw(red)/sl until every thread is done with them
}

// ---------------- init kernels ----------------
__global__ void k_mean(const float* __restrict__ feat, const float* __restrict__ emb) {
    int idx = blockIdx.x * blockDim.x + threadIdx.x;
    if (idx == 0) g_bar = 0u;
    if (idx < Bc * Ec) g_x[idx] = emb[(size_t)SOSc * Ec + (idx % Ec)];
    if (idx >= Bc * Fc) return;
    int b = idx / Fc, f = idx % Fc;
    float s = 0.f;
    const float* p = feat + (size_t)b * Nc * Fc + f;
#pragma unroll 8
    for (int n = 0; n < Nc; n++) s += p[(size_t)n * Fc];
    g_mean[idx] = s * (1.0f / 64.0f);
}

__global__ void k_h0c0(const float* __restrict__ Wh, const float* __restrict__ bh,
                       const float* __restrict__ Wc, const float* __restrict__ bc) {
    __shared__ __align__(16) float sm[64 * 36];
    int tid = threadIdx.x;
    int colg = blockIdx.x * 64 + (tid & 63);
    int bgrp = tid >> 6;
    float acc[8] = {0, 0, 0, 0, 0, 0, 0, 0};
    const float* W; float bias; float* dst;
    if (colg < Hc) { W = Wh + colg; bias = bh[colg]; dst = g_h[0] + colg; }
    else { W = Wc + (colg - Hc); bias = bc[colg - Hc]; dst = g_c[0] + (colg - Hc); }
    for (int kc = 0; kc < Fc; kc += 64) {
        __syncthreads();
        for (int e = tid; e < 2048; e += 256) {
            int kk = e >> 5, b = e & 31;
            sm[kk * 36 + b] = g_mean[b * Fc + kc + kk];
        }
        __syncthreads();
#pragma unroll 8
        for (int kk = 0; kk < 64; kk++) {
            float w = W[(size_t)(kc + kk) * Hc];
            const float* xr = &sm[kk * 36 + bgrp * 8];
#pragma unroll
            for (int i = 0; i < 8; i++) acc[i] = fmaf(xr[i], w, acc[i]);
        }
    }
#pragma unroll
    for (int i = 0; i < 8; i++) dst[(bgrp * 8 + i) * Hc] = acc[i] + bias;
}

__global__ void k_encproj(const float* __restrict__ feat, const float* __restrict__ W2,
                          const float* __restrict__ b2) {
    int tid = threadIdx.x;
    int rowbase = blockIdx.x * 64;
    int colbase = blockIdx.y * 64;
    int col = colbase + (tid & 63);
    int rgrp = tid >> 6;
    float acc[16];
#pragma unroll
    for (int i = 0; i < 16; i++) acc[i] = 0.f;
    __shared__ float As[64][33];
    __shared__ float Ws[32][65];
    for (int kc = 0; kc < Fc; kc += 32) {
        for (int e = tid; e < 64 * 32; e += 256) {
            int r = e >> 5, kk = e & 31;
            As[r][kk] = feat[(size_t)(rowbase + r) * Fc + kc + kk];
        }
        for (int e = tid; e < 32 * 64; e += 256) {
            int kk = e >> 6, c = e & 63;
            Ws[kk][c] = W2[(size_t)(kc + kk) * Hc + colbase + c];
        }
        __syncthreads();
#pragma unroll 8
        for (int kk = 0; kk < 32; kk++) {
            float w = Ws[kk][tid & 63];
#pragma unroll
            for (int i = 0; i < 16; i++) acc[i] += As[rgrp * 16 + i][kk] * w;
        }
        __syncthreads();
    }
    float bb = b2[col];
#pragma unroll
    for (int i = 0; i < 16; i++)
        g_encproj[(size_t)(rowbase + rgrp * 16 + i) * Hc + col] = acc[i] + bb;
}

// ---------------- persistent kernel ----------------
__global__ void __launch_bounds__(TPB, 1) k_persist(
    const float* __restrict__ feat, const float* __restrict__ emb,
    const float* __restrict__ W1, const float* __restrict__ b1,
    const float* __restrict__ Va, const float* __restrict__ bVa,
    const float* __restrict__ Wg, const float* __restrict__ bg,
    const float* __restrict__ Wx, const float* __restrict__ Whh,
    const float* __restrict__ blstm, const float* __restrict__ Wout,
    const float* __restrict__ bout, float* __restrict__ dout)
{
    extern __shared__ __align__(16) float dsm[];
    float* sw   = dsm;                            // 16384
    float* sb   = dsm + 16384;                    // 4608
    float* sl   = sb + 4608;                      // 4096
    float* sred = sl + 4096;                      // 1024
    int*  sredi = (int*)(sred + 1024);            // 1024
    float* s_aux = (float*)(sredi + 1024);        // 8

    const int bid = blockIdx.x;
    const int tid = threadIdx.x;

    // ===== pre-loop: hq(0)/glin(0)/gates-h(0) from h(0) =====
    if (bid < 30) {
        int u = bid;
        if (u < 4) {
            int col0 = u * 128;
            unit_g<4, 0, false>(sw, sb, sl, W1, Hc, 0, col0, Hc, g_h[0], b1 + col0,
                                g_hq + col0, Hc, nullptr, 0, 0, tid);
        } else if (u < 14) {
            int col0 = (u - 4) * 128;
            unit_g<4, 0, false>(sw, sb, sl, Wg, Fc, 0, col0, Fc, g_h[0], bg + col0,
                                g_glin + col0, Fc, nullptr, 0, 0, tid);
        } else {
            int col0 = (u - 14) * 128;
            unit_g<4, 0, false>(sw, sb, sl, Whh, G4, 0, col0, G4, g_h[0], nullptr,
                                g_gh + col0, G4, nullptr, 0, 0, tid);
        }
    }
    gridbar();

    for (int t = 0; t < Tc; t++) {
        const int rp = t & 1, wp = rp ^ 1;

        // ===== PHASE A: attention (0..127) || argmax(t-1)->x (128..135) =====
        if (bid < 128) {
            int b = bid >> 2, sub = bid & 3;
            if (tid < Hc) sl[tid] = __ldcg(&g_hq[b * Hc + tid]);
            __syncthreads();
            int warp = tid >> 5, lane = tid & 31;
#pragma unroll
            for (int ni = 0; ni < 2; ni++) {
                int n = warp + ni * 32;
                const float* ep = g_encproj + (size_t)(b * Nc + n) * Hc;
                float acc = 0.f;
#pragma unroll 4
                for (int k = lane; k < Hc; k += 32) {
                    float v = sl[k] + ep[k];
                    acc = fmaf(fmaxf(v, 0.f), Va[k], acc);
                }
#pragma unroll
                for (int o = 16; o; o >>= 1) acc += __shfl_down_sync(0xffffffffu, acc, o);
                if (lane == 0) sred[n] = acc + bVa[0];
            }
            __syncthreads();
            if (tid < 64) {
                float m = sred[tid];
#pragma unroll
                for (int o = 16; o; o >>= 1) m = fmaxf(m, __shfl_xor_sync(0xffffffffu, m, o));
                if (lane == 0) s_aux[tid >> 5] = m;
            }
            __syncthreads();
            if (tid < 64) {
                float M = fmaxf(s_aux[0], s_aux[1]);
                float e = expf(sred[tid] - M);
                sred[tid] = e;
                float ss = e;
#pragma unroll
                for (int o = 16; o; o >>= 1) ss += __shfl_xor_sync(0xffffffffu, ss, o);
                if (lane == 0) s_aux[2 + (tid >> 5)] = ss;
            }
            __syncthreads();
            if (tid < 64) {
                float wv = sred[tid] / (s_aux[2] + s_aux[3]);
                sred[tid] = wv;
                if (sub == 0)
                    dout[AOFF + (size_t)b * Tc * Nc + (size_t)t * Nc + tid] = wv;
            }
            __syncthreads();
            if (tid < 320) {
                int f = sub * 320 + tid;
                const float* fb = feat + (size_t)b * Nc * Fc + f;
                float acc = 0.f;
#pragma unroll 8
                for (int n = 0; n < 64; n++) acc = fmaf(fb[(size_t)n * Fc], sred[n], acc);
                float gl = __ldcg(&g_glin[b * Fc + f]);
                g_ctx[b * Fc + f] = acc * sigf(gl);
            }
        } else if (bid < 136 && t > 0) {
            // 8 blocks x 4 batches (256-thread quarters)
            int i = bid - 128;
            int q = tid >> 8, lt2 = tid & 255;
            int b = i * 4 + q;
            float bv = -INFINITY; int bi2 = 0x7fffffff;
            if (lt2 < NT79) {
                bv = __ldcg(&g_pbv[lt2 * 32 + b]);
                bi2 = __ldcg(&g_pbi[lt2 * 32 + b]);
            }
            sred[tid] = bv; sredi[tid] = bi2;
            __syncthreads();
            for (int o = 128; o; o >>= 1) {
                if (lt2 < o) {
                    if (sred[tid + o] > sred[tid] ||
                        (sred[tid + o] == sred[tid] && sredi[tid + o] < sredi[tid])) {
                        sred[tid] = sred[tid + o];
                        sredi[tid] = sredi[tid + o];
                    }
                }
                __syncthreads();
            }
            int best = sredi[q * 256];
            for (int e = lt2; e < Ec; e += 256)
                g_x[b * Ec + e] = emb[(size_t)best * Ec + e];
        }
        gridbar();

        // ===== PHASE C: gates x/ctx part: 16 tiles x 14 K-chunks(128) = 224 units =====
        for (int u = bid; u < 224; u += NBLK) {
            int tile = u / 14, kch = u % 14;
            unit_g<1, 1, false>(sw, sb, sl, Wx, G4, kch * 128, tile * 128, G4,
                                nullptr, nullptr, g_gp[kch] + tile * 128, G4,
                                nullptr, 0, 0, tid);
        }
        gridbar();

        // ===== PHASE D: LSTM pointwise (g_gh + 14 partials), 16 blocks =====
        if (bid < 16) {
            int id = bid * TPB + tid;           // 0..16383
            int b = id >> 9, j = id & 511;
            float gi = blstm[j]          + __ldcg(&g_gh[(size_t)b * G4 + j]);
            float gf = blstm[Hc + j]     + __ldcg(&g_gh[(size_t)b * G4 + Hc + j]);
            float gg = blstm[2 * Hc + j] + __ldcg(&g_gh[(size_t)b * G4 + 2 * Hc + j]);
            float go = blstm[3 * Hc + j] + __ldcg(&g_gh[(size_t)b * G4 + 3 * Hc + j]);
#pragma unroll
            for (int p = 0; p < 14; p++) {
                const float* gp = g_gp[p] + (size_t)b * G4;
                gi += __ldcg(&gp[j]);
                gf += __ldcg(&gp[Hc + j]);
                gg += __ldcg(&gp[2 * Hc + j]);
                go += __ldcg(&gp[3 * Hc + j]);
            }
            float cprev = g_c[rp][b * Hc + j];
            float iv = sigf(gi), fv = sigf(gf), gv = tanhf(gg), ov = sigf(go);
            float c2 = fv * cprev + iv * gv;
            float h2 = ov * tanhf(c2);
            g_c[wp][b * Hc + j] = c2;
            g_h[wp][b * Hc + j] = h2;
            if (t == Tc - 1) {
                dout[HOFF + b * Hc + j] = h2;
                dout[COFF + b * Hc + j] = c2;
            }
        }
        gridbar();

        // ===== PHASE E: logits(t) [79 tiles] || hq/glin/gates-h(t+1) [30 units] =====
        if (bid < NT79) {
            unit_g<4, 0, true>(sw, sb, sl, Wout, Vc, 0, bid * 128, Vc, g_h[wp],
                               bout + bid * 128, nullptr, 0, dout, t, bid, tid);
        } else if (bid < 109) {
            int u = bid - NT79;
            if (u < 4) {
                int col0 = u * 128;
                unit_g<4, 0, false>(sw, sb, sl, W1, Hc, 0, col0, Hc, g_h[wp], b1 + col0,
                                    g_hq + col0, Hc, nullptr, 0, 0, tid);
            } else if (u < 14) {
                int col0 = (u - 4) * 128;
                unit_g<4, 0, false>(sw, sb, sl, Wg, Fc, 0, col0, Fc, g_h[wp], bg + col0,
                                    g_glin + col0, Fc, nullptr, 0, 0, tid);
            } else {
                int col0 = (u - 14) * 128;
                unit_g<4, 0, false>(sw, sb, sl, Whh, G4, 0, col0, G4, g_h[wp], nullptr,
                                    g_gh + col0, G4, nullptr, 0, 0, tid);
            }
        }
        gridbar();
    }
}

// ---------------- launcher ----------------
extern "C" void kernel_launch(void* const* d_in, const int* in_sizes, int n_in,
                              void* d_out, int out_size) {
    int off = (n_in > 2 && in_sizes[2] == 1) ? 1 : 0;
    const float* feat  = (const float*)d_in[0];
    const float* emb   = (const float*)d_in[2 + off];
    const float* W1    = (const float*)d_in[3 + off];
    const float* b1    = (const float*)d_in[4 + off];
    const float* W2    = (const float*)d_in[5 + off];
    const float* b2    = (const float*)d_in[6 + off];
    const float* Va    = (const float*)d_in[7 + off];
    const float* bVa   = (const float*)d_in[8 + off];
    const float* Wh    = (const float*)d_in[9 + off];
    const float* bh    = (const float*)d_in[10 + off];
    const float* Wc    = (const float*)d_in[11 + off];
    const float* bc    = (const float*)d_in[12 + off];
    const float* Wg    = (const float*)d_in[13 + off];
    const float* bg    = (const float*)d_in[14 + off];
    const float* Wx    = (const float*)d_in[15 + off];
    const float* Whh   = (const float*)d_in[16 + off];
    const float* blstm = (const float*)d_in[17 + off];
    const float* Wout  = (const float*)d_in[18 + off];
    const float* bout  = (const float*)d_in[19 + off];
    float* out = (float*)d_out;

    cudaFuncSetAttribute(k_persist, cudaFuncAttributeMaxDynamicSharedMemorySize, SMEM_BYTES);

    k_mean<<<160, 256>>>(feat, emb);
    k_h0c0<<<16, 256>>>(Wh, bh, Wc, bc);
    k_encproj<<<dim3(32, 8), 256>>>(feat, W2, b2);
    k_persist<<<NBLK, TPB, SMEM_BYTES>>>(feat, emb, W1, b1, Va, bVa, Wg, bg,
                                         Wx, Whh, blstm, Wout, bout, out);
}

// round 14
// speedup vs baseline: 1.0114x; 1.0036x over previous
#include <cuda_runtime.h>
#include <cuda_bf16.h>
#include <math.h>

#define Bc 32
#define Nc 64
#define Fc 1280
#define Hc 512
#define Ec 512
#define Vc 10000
#define Tc 80
#define SOSc 1
#define G4 2048
#define NBLK 148
#define TPB 512
#define NT79 79

typedef unsigned long long ull;

// ---------------- device scratch ----------------
__device__ float g_h[2][Bc * Hc];
__device__ float g_c[2][Bc * Hc];
__device__ float g_x[Bc * Ec];
__device__ float g_hq[Bc * Hc];        // full hq (bias included)
__device__ float g_glin[Bc * Fc];      // full glin (bias included)
__device__ float g_gh[Bc * G4];        // full gates h-part
__device__ float g_ctx[Bc * Fc];
__device__ float g_encproj[Bc * Nc * Hc];
__device__ float g_mean[Bc * Fc];
__device__ float g_gp[7][Bc * G4];     // gates x-part partials (K-split 7 x 256)
__device__ float g_pbv[NT79 * Bc];
__device__ int   g_pbi[NT79 * Bc];
__device__ unsigned g_bar;

#define HOFF ((size_t)Bc * Tc * Vc)
#define COFF (HOFF + (size_t)Bc * Hc)
#define AOFF (COFF + (size_t)Bc * Hc)

// dynamic smem carve (floats): sw 16384 | sb 4608 | sl 4096 | sred 512 | sredi 512 | aux 8
#define SMEM_FLOATS (16384 + 4608 + 4096 + 512 + 512 + 8)
#define SMEM_BYTES (SMEM_FLOATS * 4)

__device__ __forceinline__ float sigf(float x) { return 1.0f / (1.0f + expf(-x)); }

__device__ __forceinline__ ull pk2(float x) {
    ull r; asm("mov.b64 %0,{%1,%1};" : "=l"(r) : "r"(__float_as_uint(x))); return r;
}
__device__ __forceinline__ void fma2(ull& d, ull a, ull b) {
    asm("fma.rn.f32x2 %0,%1,%2,%0;" : "+l"(d) : "l"(a), "l"(b));
}
__device__ __forceinline__ ull add2(ull a, ull b) {
    ull d; asm("add.rn.f32x2 %0,%1,%2;" : "=l"(d) : "l"(a), "l"(b)); return d;
}
__device__ __forceinline__ float2 un2(ull v) {
    unsigned lo, hi; asm("mov.b64 {%0,%1},%2;" : "=r"(lo), "=r"(hi) : "l"(v));
    float2 f; f.x = __uint_as_float(lo); f.y = __uint_as_float(hi); return f;
}

__device__ __forceinline__ void gridbar() {
    __syncthreads();
    if (threadIdx.x == 0) {
        __threadfence();
        unsigned t = atomicAdd(&g_bar, 1u) + 1u;
        unsigned target = ((t + NBLK - 1u) / NBLK) * NBLK;
        while (*((volatile unsigned*)&g_bar) < target) __nanosleep(32);
        __threadfence();
    }
    __syncthreads();
}

// ================= unified full-tile GEMM unit, register double-buffered =========
// C[32 x 128cols] over NCH chunks of 128 k. 4 K-planes (tid>>7) x 128 threads.
// Thread tile: 4 cols x 8 batches (16 ull accumulators).
// Staging: each thread prefetches next chunk's weights (8 x float4) and operand
// (8 x float) into REGISTERS before the compute loop of the current chunk, so the
// LDG round-trip overlaps the FFMA2 burst. Commit to smem is plain STS.
// SRCMODE 0: operand hsrc[b*Hc + k]; SRCMODE 1: x/ctx concat at global k.
template <int NCH, int SRCMODE, bool LOGITS>
__device__ __forceinline__ void unit_fk(
    float* sw, float* sb, float* sl,
    const float* __restrict__ W, size_t ldw, int kbase, int col0, int maxc,
    const float* __restrict__ hsrc, const float* __restrict__ bias,
    float* dstp, size_t dst_stride,
    float* __restrict__ dout, int t, int tile, int tid)
{
    const int ks = tid >> 7;            // plane 0..3
    const int lt = tid & 127;
    const int wrp = lt >> 5, lane = lt & 31;
    const int ct = wrp * 8 + (lane & 7);    // 0..31 col-thread
    const int bg = lane >> 3;               // 0..3 batch-group (8 batches)
    const int c4 = ct << 2, b8 = bg << 3;
    const int warp32 = tid >> 5, lane2 = tid & 31;
    const int maxc4 = maxc - 4;
    ull A[16];
#pragma unroll
    for (int i = 0; i < 16; i++) A[i] = 0;

    float4 wreg[8];
    float  breg[8];
    // prologue: prefetch chunk 0
    {
        const int kc = kbase;
#pragma unroll
        for (int i = 0; i < 8; i++) {
            int e = tid + i * TPB;
            int kk = e >> 5, cc = (e & 31) << 2;
            int cg = col0 + cc; if (cg > maxc4) cg = maxc4;
            wreg[i] = *(const float4*)&W[(size_t)(kc + kk) * ldw + cg];
        }
#pragma unroll
        for (int i = 0; i < 8; i++) {
            int idx = warp32 + i * 16;
            int b = idx & 31, kkc = (idx >> 5) << 5;
            int k = kc + kkc + lane2;
            if (SRCMODE == 0) breg[i] = __ldcg(&hsrc[b * Hc + k]);
            else breg[i] = (k < Ec) ? __ldcg(&g_x[b * Ec + k])
                                    : __ldcg(&g_ctx[b * Fc + (k - Ec)]);
        }
    }
#pragma unroll
    for (int ch = 0; ch < NCH; ch++) {
        // commit prefetched chunk ch to smem
#pragma unroll
        for (int i = 0; i < 8; i++) {
            int e = tid + i * TPB;
            int kk = e >> 5, cc = (e & 31) << 2;
            *(float4*)&sw[kk * 128 + cc] = wreg[i];
        }
#pragma unroll
        for (int i = 0; i < 8; i++) {
            int idx = warp32 + i * 16;
            int b = idx & 31, kkc = (idx >> 5) << 5;
            sb[(kkc + lane2) * 36 + b] = breg[i];
        }
        __syncthreads();
        // prefetch chunk ch+1 into registers (overlaps the compute below)
        if (ch + 1 < NCH) {
            const int kc = kbase + (ch + 1) * 128;
#pragma unroll
            for (int i = 0; i < 8; i++) {
                int e = tid + i * TPB;
                int kk = e >> 5, cc = (e & 31) << 2;
                int cg = col0 + cc; if (cg > maxc4) cg = maxc4;
                wreg[i] = *(const float4*)&W[(size_t)(kc + kk) * ldw + cg];
            }
#pragma unroll
            for (int i = 0; i < 8; i++) {
                int idx = warp32 + i * 16;
                int b = idx & 31, kkc = (idx >> 5) << 5;
                int k = kc + kkc + lane2;
                if (SRCMODE == 0) breg[i] = __ldcg(&hsrc[b * Hc + k]);
                else breg[i] = (k < Ec) ? __ldcg(&g_x[b * Ec + k])
                                        : __ldcg(&g_ctx[b * Fc + (k - Ec)]);
            }
        }
        // compute chunk ch (plane ks handles 32 of the 128 kk)
        {
            const float* swp = sw + (ks * 32) * 128 + c4;
            const float* sbp = sb + (ks * 32) * 36 + b8;
#pragma unroll 8
            for (int kk = 0; kk < 32; kk++) {
                float4 w = *(const float4*)(swp + kk * 128);
                ulonglong2 b01 = *(const ulonglong2*)(sbp + kk * 36);
                ulonglong2 b23 = *(const ulonglong2*)(sbp + kk * 36 + 4);
                ull w0 = pk2(w.x), w1 = pk2(w.y), w2 = pk2(w.z), w3 = pk2(w.w);
                fma2(A[0],  w0, b01.x); fma2(A[1],  w1, b01.x);
                fma2(A[2],  w2, b01.x); fma2(A[3],  w3, b01.x);
                fma2(A[4],  w0, b01.y); fma2(A[5],  w1, b01.y);
                fma2(A[6],  w2, b01.y); fma2(A[7],  w3, b01.y);
                fma2(A[8],  w0, b23.x); fma2(A[9],  w1, b23.x);
                fma2(A[10], w2, b23.x); fma2(A[11], w3, b23.x);
                fma2(A[12], w0, b23.y); fma2(A[13], w1, b23.y);
                fma2(A[14], w2, b23.y); fma2(A[15], w3, b23.y);
            }
        }
        __syncthreads();   // protect sw/sb before next commit
    }
    // plane reduce through sw (weights no longer needed)
    ull* red = (ull*)sw;
    if (ks > 0) {
#pragma unroll
        for (int i = 0; i < 16; i++) red[((ks - 1) * 128 + lt) * 16 + i] = A[i];
    }
    __syncthreads();
    if (ks == 0) {
#pragma unroll
        for (int p = 0; p < 3; p++)
#pragma unroll
            for (int i = 0; i < 16; i++)
                A[i] = add2(A[i], red[(p * 128 + lt) * 16 + i]);
        float vals[8][4];
#pragma unroll
        for (int bp = 0; bp < 4; bp++)
#pragma unroll
            for (int c = 0; c < 4; c++) {
                float2 q = un2(A[bp * 4 + c]);
                vals[bp * 2 + 0][c] = q.x;
                vals[bp * 2 + 1][c] = q.y;
            }
        if (!LOGITS) {
            float4 bb = make_float4(0.f, 0.f, 0.f, 0.f);
            if (bias) bb = *(const float4*)&bias[c4];
#pragma unroll
            for (int i = 0; i < 8; i++) {
                int b = b8 + i;
                *(float4*)&dstp[(size_t)b * dst_stride + c4] =
                    make_float4(vals[i][0] + bb.x, vals[i][1] + bb.y,
                                vals[i][2] + bb.z, vals[i][3] + bb.w);
            }
        } else {
#pragma unroll
            for (int i = 0; i < 8; i++) {
                int b = b8 + i;
#pragma unroll
                for (int c = 0; c < 4; c++) {
                    int col = col0 + c4 + c;
                    float v = -INFINITY;
                    if (col < Vc) {
                        v = vals[i][c] + bias[c4 + c];
                        dout[(size_t)b * Tc * Vc + (size_t)t * Vc + col] = v;
                    }
                    sl[b * 128 + c4 + c] = v;
                }
            }
        }
    }
    if (LOGITS) {
        __syncthreads();
        if (tid < 32) {
            int b = tid;
            float bv = -INFINITY; int bi = 0;
#pragma unroll 8
            for (int cq = 0; cq < 128; cq++) {
                float v = sl[b * 128 + cq];
                if (v > bv) { bv = v; bi = col0 + cq; }
            }
            g_pbv[tile * 32 + b] = bv;
            g_pbi[tile * 32 + b] = bi;
        }
    }
    __syncthreads();   // protect sw(red)/sl until every thread is done
}

// ---------------- init kernels ----------------
__global__ void k_mean(const float* __restrict__ feat, const float* __restrict__ emb) {
    int idx = blockIdx.x * blockDim.x + threadIdx.x;
    if (idx == 0) g_bar = 0u;
    if (idx < Bc * Ec) g_x[idx] = emb[(size_t)SOSc * Ec + (idx % Ec)];
    if (idx >= Bc * Fc) return;
    int b = idx / Fc, f = idx % Fc;
    float s = 0.f;
    const float* p = feat + (size_t)b * Nc * Fc + f;
#pragma unroll 8
    for (int n = 0; n < Nc; n++) s += p[(size_t)n * Fc];
    g_mean[idx] = s * (1.0f / 64.0f);
}

__global__ void k_h0c0(const float* __restrict__ Wh, const float* __restrict__ bh,
                       const float* __restrict__ Wc, const float* __restrict__ bc) {
    __shared__ __align__(16) float sm[64 * 36];
    int tid = threadIdx.x;
    int colg = blockIdx.x * 64 + (tid & 63);
    int bgrp = tid >> 6;
    float acc[8] = {0, 0, 0, 0, 0, 0, 0, 0};
    const float* W; float bias; float* dst;
    if (colg < Hc) { W = Wh + colg; bias = bh[colg]; dst = g_h[0] + colg; }
    else { W = Wc + (colg - Hc); bias = bc[colg - Hc]; dst = g_c[0] + (colg - Hc); }
    for (int kc = 0; kc < Fc; kc += 64) {
        __syncthreads();
        for (int e = tid; e < 2048; e += 256) {
            int kk = e >> 5, b = e & 31;
            sm[kk * 36 + b] = g_mean[b * Fc + kc + kk];
        }
        __syncthreads();
#pragma unroll 8
        for (int kk = 0; kk < 64; kk++) {
            float w = W[(size_t)(kc + kk) * Hc];
            const float* xr = &sm[kk * 36 + bgrp * 8];
#pragma unroll
            for (int i = 0; i < 8; i++) acc[i] = fmaf(xr[i], w, acc[i]);
        }
    }
#pragma unroll
    for (int i = 0; i < 8; i++) dst[(bgrp * 8 + i) * Hc] = acc[i] + bias;
}

__global__ void k_encproj(const float* __restrict__ feat, const float* __restrict__ W2,
                          const float* __restrict__ b2) {
    int tid = threadIdx.x;
    int rowbase = blockIdx.x * 64;
    int colbase = blockIdx.y * 64;
    int col = colbase + (tid & 63);
    int rgrp = tid >> 6;
    float acc[16];
#pragma unroll
    for (int i = 0; i < 16; i++) acc[i] = 0.f;
    __shared__ float As[64][33];
    __shared__ float Ws[32][65];
    for (int kc = 0; kc < Fc; kc += 32) {
        for (int e = tid; e < 64 * 32; e += 256) {
            int r = e >> 5, kk = e & 31;
            As[r][kk] = feat[(size_t)(rowbase + r) * Fc + kc + kk];
        }
        for (int e = tid; e < 32 * 64; e += 256) {
            int kk = e >> 6, c = e & 63;
            Ws[kk][c] = W2[(size_t)(kc + kk) * Hc + colbase + c];
        }
        __syncthreads();
#pragma unroll 8
        for (int kk = 0; kk < 32; kk++) {
            float w = Ws[kk][tid & 63];
#pragma unroll
            for (int i = 0; i < 16; i++) acc[i] += As[rgrp * 16 + i][kk] * w;
        }
        __syncthreads();
    }
    float bb = b2[col];
#pragma unroll
    for (int i = 0; i < 16; i++)
        g_encproj[(size_t)(rowbase + rgrp * 16 + i) * Hc + col] = acc[i] + bb;
}

// ---------------- persistent kernel ----------------
__global__ void __launch_bounds__(TPB, 1) k_persist(
    const float* __restrict__ feat, const float* __restrict__ emb,
    const float* __restrict__ W1, const float* __restrict__ b1,
    const float* __restrict__ Va, const float* __restrict__ bVa,
    const float* __restrict__ Wg, const float* __restrict__ bg,
    const float* __restrict__ Wx, const float* __restrict__ Whh,
    const float* __restrict__ blstm, const float* __restrict__ Wout,
    const float* __restrict__ bout, float* __restrict__ dout)
{
    extern __shared__ __align__(16) float dsm[];
    float* sw   = dsm;                            // 16384
    float* sb   = dsm + 16384;                    // 4608
    float* sl   = sb + 4608;                      // 4096
    float* sred = sl + 4096;                      // 512
    int*  sredi = (int*)(sred + 512);             // 512
    float* s_aux = (float*)(sredi + 512);         // 8

    const int bid = blockIdx.x;
    const int tid = threadIdx.x;

    // ===== pre-loop: hq(0)/glin(0)/gates-h(0) from h(0) =====
    if (bid < 30) {
        int u = bid;
        if (u < 4) {
            int col0 = u * 128;
            unit_fk<4, 0, false>(sw, sb, sl, W1, Hc, 0, col0, Hc, g_h[0], b1 + col0,
                                 g_hq + col0, Hc, nullptr, 0, 0, tid);
        } else if (u < 14) {
            int col0 = (u - 4) * 128;
            unit_fk<4, 0, false>(sw, sb, sl, Wg, Fc, 0, col0, Fc, g_h[0], bg + col0,
                                 g_glin + col0, Fc, nullptr, 0, 0, tid);
        } else {
            int col0 = (u - 14) * 128;
            unit_fk<4, 0, false>(sw, sb, sl, Whh, G4, 0, col0, G4, g_h[0], nullptr,
                                 g_gh + col0, G4, nullptr, 0, 0, tid);
        }
    }
    gridbar();

    for (int t = 0; t < Tc; t++) {
        const int rp = t & 1, wp = rp ^ 1;

        // ===== PHASE A: attention (0..127) || argmax(t-1)->x (128..147) =====
        if (bid < 128) {
            int b = bid >> 2, sub = bid & 3;
            sl[tid] = __ldcg(&g_hq[b * Hc + tid]);   // Hc == TPB, bias included
            __syncthreads();
            int warp = tid >> 5, lane = tid & 31;
#pragma unroll
            for (int ni = 0; ni < 4; ni++) {
                int n = warp + ni * 16;
                const float* ep = g_encproj + (size_t)(b * Nc + n) * Hc;
                float acc = 0.f;
#pragma unroll 4
                for (int k = lane; k < Hc; k += 32) {
                    float v = sl[k] + ep[k];
                    acc = fmaf(fmaxf(v, 0.f), Va[k], acc);
                }
#pragma unroll
                for (int o = 16; o; o >>= 1) acc += __shfl_down_sync(0xffffffffu, acc, o);
                if (lane == 0) sred[n] = acc + bVa[0];
            }
            __syncthreads();
            if (tid < 64) {
                float m = sred[tid];
#pragma unroll
                for (int o = 16; o; o >>= 1) m = fmaxf(m, __shfl_xor_sync(0xffffffffu, m, o));
                if (lane == 0) s_aux[tid >> 5] = m;
            }
            __syncthreads();
            if (tid < 64) {
                float M = fmaxf(s_aux[0], s_aux[1]);
                float e = expf(sred[tid] - M);
                sred[tid] = e;
                float ss = e;
#pragma unroll
                for (int o = 16; o; o >>= 1) ss += __shfl_xor_sync(0xffffffffu, ss, o);
                if (lane == 0) s_aux[2 + (tid >> 5)] = ss;
            }
            __syncthreads();
            if (tid < 64) {
                float wv = sred[tid] / (s_aux[2] + s_aux[3]);
                sred[tid] = wv;
                if (sub == 0)
                    dout[AOFF + (size_t)b * Tc * Nc + (size_t)t * Nc + tid] = wv;
            }
            __syncthreads();
            if (tid < 320) {
                int f = sub * 320 + tid;
                const float* fb = feat + (size_t)b * Nc * Fc + f;
                float acc = 0.f;
#pragma unroll 8
                for (int n = 0; n < 64; n++) acc = fmaf(fb[(size_t)n * Fc], sred[n], acc);
                float gl = __ldcg(&g_glin[b * Fc + f]);
                g_ctx[b * Fc + f] = acc * sigf(gl);
            }
        } else if (t > 0) {
            int i = bid - 128;
            int half = tid >> 8, lt2 = tid & 255;
            int b = (i < 12) ? (2 * i + half) : (24 + (i - 12));
            bool active = (i < 12) || (half == 0);
            float bv = -INFINITY; int bi2 = 0x7fffffff;
            if (active && lt2 < NT79) {
                bv = __ldcg(&g_pbv[lt2 * 32 + b]);
                bi2 = __ldcg(&g_pbi[lt2 * 32 + b]);
            }
            sred[tid] = bv; sredi[tid] = bi2;
            __syncthreads();
            for (int o = 128; o; o >>= 1) {
                if (lt2 < o) {
                    if (sred[tid + o] > sred[tid] ||
                        (sred[tid + o] == sred[tid] && sredi[tid + o] < sredi[tid])) {
                        sred[tid] = sred[tid + o];
                        sredi[tid] = sredi[tid + o];
                    }
                }
                __syncthreads();
            }
            if (active) {
                int best = sredi[half * 256];
                for (int e = lt2; e < Ec; e += 256)
                    g_x[b * Ec + e] = emb[(size_t)best * Ec + e];
            }
        }
        gridbar();

        // ===== PHASE C: gates x/ctx part: 16 tiles x 7 K-chunks(256) = 112 units =====
        if (bid < 112) {
            int tile = bid / 7, kch = bid % 7;
            unit_fk<2, 1, false>(sw, sb, sl, Wx, G4, kch * 256, tile * 128, G4,
                                 nullptr, nullptr, g_gp[kch] + tile * 128, G4,
                                 nullptr, 0, 0, tid);
        }
        gridbar();

        // ===== PHASE D: LSTM pointwise (g_gh + 7 partials) =====
        if (bid < 32) {
            int id = bid * TPB + tid;          // 0..16383
            int b = id >> 9, j = id & 511;
            float gi = blstm[j]          + __ldcg(&g_gh[(size_t)b * G4 + j]);
            float gf = blstm[Hc + j]     + __ldcg(&g_gh[(size_t)b * G4 + Hc + j]);
            float gg = blstm[2 * Hc + j] + __ldcg(&g_gh[(size_t)b * G4 + 2 * Hc + j]);
            float go = blstm[3 * Hc + j] + __ldcg(&g_gh[(size_t)b * G4 + 3 * Hc + j]);
#pragma unroll
            for (int p = 0; p < 7; p++) {
                const float* gp = g_gp[p] + (size_t)b * G4;
                gi += __ldcg(&gp[j]);
                gf += __ldcg(&gp[Hc + j]);
                gg += __ldcg(&gp[2 * Hc + j]);
                go += __ldcg(&gp[3 * Hc + j]);
            }
            float cprev = g_c[rp][b * Hc + j];
            float iv = sigf(gi), fv = sigf(gf), gv = tanhf(gg), ov = sigf(go);
            float c2 = fv * cprev + iv * gv;
            float h2 = ov * tanhf(c2);
            g_c[wp][b * Hc + j] = c2;
            g_h[wp][b * Hc + j] = h2;
            if (t == Tc - 1) {
                dout[HOFF + b * Hc + j] = h2;
                dout[COFF + b * Hc + j] = c2;
            }
        }
        gridbar();

        // ===== PHASE E: logits(t) [79 tiles] || hq/glin/gates-h(t+1) [30 units] =====
        if (bid < NT79) {
            unit_fk<4, 0, true>(sw, sb, sl, Wout, Vc, 0, bid * 128, Vc, g_h[wp],
                                bout + bid * 128, nullptr, 0, dout, t, bid, tid);
        } else if (bid < 109) {
            int u = bid - NT79;
            if (u < 4) {
                int col0 = u * 128;
                unit_fk<4, 0, false>(sw, sb, sl, W1, Hc, 0, col0, Hc, g_h[wp], b1 + col0,
                                     g_hq + col0, Hc, nullptr, 0, 0, tid);
            } else if (u < 14) {
                int col0 = (u - 4) * 128;
                unit_fk<4, 0, false>(sw, sb, sl, Wg, Fc, 0, col0, Fc, g_h[wp], bg + col0,
                                     g_glin + col0, Fc, nullptr, 0, 0, tid);
            } else {
                int col0 = (u - 14) * 128;
                unit_fk<4, 0, false>(sw, sb, sl, Whh, G4, 0, col0, G4, g_h[wp], nullptr,
                                     g_gh + col0, G4, nullptr, 0, 0, tid);
            }
        }
        gridbar();
    }
}

// ---------------- launcher ----------------
extern "C" void kernel_launch(void* const* d_in, const int* in_sizes, int n_in,
                              void* d_out, int out_size) {
    int off = (n_in > 2 && in_sizes[2] == 1) ? 1 : 0;
    const float* feat  = (const float*)d_in[0];
    const float* emb   = (const float*)d_in[2 + off];
    const float* W1    = (const float*)d_in[3 + off];
    const float* b1    = (const float*)d_in[4 + off];
    const float* W2    = (const float*)d_in[5 + off];
    const float* b2    = (const float*)d_in[6 + off];
    const float* Va    = (const float*)d_in[7 + off];
    const float* bVa   = (const float*)d_in[8 + off];
    const float* Wh    = (const float*)d_in[9 + off];
    const float* bh    = (const float*)d_in[10 + off];
    const float* Wc    = (const float*)d_in[11 + off];
    const float* bc    = (const float*)d_in[12 + off];
    const float* Wg    = (const float*)d_in[13 + off];
    const float* bg    = (const float*)d_in[14 + off];
    const float* Wx    = (const float*)d_in[15 + off];
    const float* Whh   = (const float*)d_in[16 + off];
    const float* blstm = (const float*)d_in[17 + off];
    const float* Wout  = (const float*)d_in[18 + off];
    const float* bout  = (const float*)d_in[19 + off];
    float* out = (float*)d_out;

    cudaFuncSetAttribute(k_persist, cudaFuncAttributeMaxDynamicSharedMemorySize, SMEM_BYTES);

    k_mean<<<160, 256>>>(feat, emb);
    k_h0c0<<<16, 256>>>(Wh, bh, Wc, bc);
    k_encproj<<<dim3(32, 8), 256>>>(feat, W2, b2);
    k_persist<<<NBLK, TPB, SMEM_BYTES>>>(feat, emb, W1, b1, Va, bVa, Wg, bg,
                                         Wx, Whh, blstm, Wout, bout, out);
}

// round 15
// speedup vs baseline: 1.0338x; 1.0222x over previous
#include <cuda_runtime.h>
#include <cuda_bf16.h>
#include <math.h>

#define Bc 32
#define Nc 64
#define Fc 1280
#define Hc 512
#define Ec 512
#define Vc 10000
#define Tc 80
#define SOSc 1
#define G4 2048
#define NBLK 148
#define TPB 512
#define NT79 79

typedef unsigned long long ull;

// ---------------- device scratch ----------------
__device__ float g_h[2][Bc * Hc];
__device__ float g_c[2][Bc * Hc];
__device__ float g_x[Bc * Ec];
__device__ float g_hq[Bc * Hc];        // full hq (bias included)
__device__ float g_glin[Bc * Fc];      // full glin (bias included)
__device__ float g_gh[Bc * G4];        // full gates h-part
__device__ float g_ctx[Bc * Fc];
__device__ float g_encproj[Bc * Nc * Hc];
__device__ float g_mean[Bc * Fc];
__device__ float g_gp[7][Bc * G4];     // gates x-part partials (K-split 7), STRIP-packed
__device__ float g_pbv[NT79 * Bc];
__device__ int   g_pbi[NT79 * Bc];
__device__ unsigned g_cnt[16];         // per-tile completion counters for C+D fusion
struct __align__(128) BarPad { unsigned v; unsigned pad[31]; };
__device__ BarPad g_bar;

#define HOFF ((size_t)Bc * Tc * Vc)
#define COFF (HOFF + (size_t)Bc * Hc)
#define AOFF (COFF + (size_t)Bc * Hc)

// dynamic smem carve (floats): sw 16384 | sb 4608 | sl 4096 | sred 512 | sredi 512 | aux 8
#define SMEM_FLOATS (16384 + 4608 + 4096 + 512 + 512 + 8)
#define SMEM_BYTES (SMEM_FLOATS * 4)

__device__ __forceinline__ float sigf(float x) { return 1.0f / (1.0f + expf(-x)); }

__device__ __forceinline__ ull pk2(float x) {
    ull r; asm("mov.b64 %0,{%1,%1};" : "=l"(r) : "r"(__float_as_uint(x))); return r;
}
__device__ __forceinline__ void fma2(ull& d, ull a, ull b) {
    asm("fma.rn.f32x2 %0,%1,%2,%0;" : "+l"(d) : "l"(a), "l"(b));
}
__device__ __forceinline__ ull add2(ull a, ull b) {
    ull d; asm("add.rn.f32x2 %0,%1,%2;" : "=l"(d) : "l"(a), "l"(b)); return d;
}
__device__ __forceinline__ float2 un2(ull v) {
    unsigned lo, hi; asm("mov.b64 {%0,%1},%2;" : "=r"(lo), "=r"(hi) : "l"(v));
    float2 f; f.x = __uint_as_float(lo); f.y = __uint_as_float(hi); return f;
}

__device__ __forceinline__ void gridbar() {
    __syncthreads();
    if (threadIdx.x == 0) {
        __threadfence();
        unsigned t = atomicAdd(&g_bar.v, 1u) + 1u;
        unsigned target = ((t + NBLK - 1u) / NBLK) * NBLK;
        while (*((volatile unsigned*)&g_bar.v) < target) {}
        __threadfence();
    }
    __syncthreads();
}

// ================= unified full-K tile GEMM unit =================
// C[32 x 128cols] over NCH chunks of 128 k. 4 K-planes (tid>>7) x 128 threads.
// Thread tile: 4 cols x 8 batches (16 ull accumulators).
// STRIP=0: cols = col0..col0+127 contiguous (clamped at maxc).
// STRIP=1: packed gate strips — packed col cc maps to (cc>>5)*512 + col0 + (cc&31)
//          (col0 = tile*32). Used for the j-grouped gates tiles.
// SRCMODE 0: operand hsrc[b*Hc + k]; SRCMODE 1: x/ctx concat at global k.
template <int NCH, int SRCMODE, bool LOGITS, int STRIP>
__device__ __forceinline__ void unit_fk(
    float* sw, float* sb, float* sl,
    const float* __restrict__ W, size_t ldw, int kbase, int col0, int maxc,
    const float* __restrict__ hsrc, const float* __restrict__ bias,
    float* dstp, size_t dst_stride,
    float* __restrict__ dout, int t, int tile, int tid)
{
    const int ks = tid >> 7;            // plane 0..3
    const int lt = tid & 127;
    const int wrp = lt >> 5, lane = lt & 31;
    const int ct = wrp * 8 + (lane & 7);    // 0..31 col-thread
    const int bg = lane >> 3;               // 0..3 batch-group (8 batches)
    const int c4 = ct << 2, b8 = bg << 3;
    const int warp32 = tid >> 5, lane2 = tid & 31;
    const int maxc4 = maxc - 4;
    ull A[16];
#pragma unroll
    for (int i = 0; i < 16; i++) A[i] = 0;

#pragma unroll
    for (int ch = 0; ch < NCH; ch++) {
        const int kc = kbase + ch * 128;
        // stage weights: 128 rows x 128 (packed) cols
#pragma unroll
        for (int e = tid; e < 4096; e += TPB) {
            int kk = e >> 5, cc = (e & 31) << 2;
            int cg;
            if (STRIP) cg = ((cc >> 5) << 9) + col0 + (cc & 31);
            else { cg = col0 + cc; if (cg > maxc4) cg = maxc4; }
            *(float4*)&sw[kk * 128 + cc] = *(const float4*)&W[(size_t)(kc + kk) * ldw + cg];
        }
        // stage operand transposed: sb[k*36 + b]
#pragma unroll
        for (int idx = warp32; idx < 128; idx += 16) {
            int b = idx & 31, kkc = (idx >> 5) << 5;
            int k = kc + kkc + lane2;
            float v;
            if (SRCMODE == 0) v = __ldcg(&hsrc[b * Hc + k]);
            else v = (k < Ec) ? __ldcg(&g_x[b * Ec + k])
                              : __ldcg(&g_ctx[b * Fc + (k - Ec)]);
            sb[(kkc + lane2) * 36 + b] = v;
        }
        __syncthreads();
        {
            const float* swp = sw + (ks * 32) * 128 + c4;
            const float* sbp = sb + (ks * 32) * 36 + b8;
#pragma unroll 8
            for (int kk = 0; kk < 32; kk++) {
                float4 w = *(const float4*)(swp + kk * 128);
                ulonglong2 b01 = *(const ulonglong2*)(sbp + kk * 36);
                ulonglong2 b23 = *(const ulonglong2*)(sbp + kk * 36 + 4);
                ull w0 = pk2(w.x), w1 = pk2(w.y), w2 = pk2(w.z), w3 = pk2(w.w);
                fma2(A[0],  w0, b01.x); fma2(A[1],  w1, b01.x);
                fma2(A[2],  w2, b01.x); fma2(A[3],  w3, b01.x);
                fma2(A[4],  w0, b01.y); fma2(A[5],  w1, b01.y);
                fma2(A[6],  w2, b01.y); fma2(A[7],  w3, b01.y);
                fma2(A[8],  w0, b23.x); fma2(A[9],  w1, b23.x);
                fma2(A[10], w2, b23.x); fma2(A[11], w3, b23.x);
                fma2(A[12], w0, b23.y); fma2(A[13], w1, b23.y);
                fma2(A[14], w2, b23.y); fma2(A[15], w3, b23.y);
            }
        }
        __syncthreads();
    }
    // plane reduce through sw (weights no longer needed)
    ull* red = (ull*)sw;
    if (ks > 0) {
#pragma unroll
        for (int i = 0; i < 16; i++) red[((ks - 1) * 128 + lt) * 16 + i] = A[i];
    }
    __syncthreads();
    if (ks == 0) {
#pragma unroll
        for (int p = 0; p < 3; p++)
#pragma unroll
            for (int i = 0; i < 16; i++)
                A[i] = add2(A[i], red[(p * 128 + lt) * 16 + i]);
        float vals[8][4];
#pragma unroll
        for (int bp = 0; bp < 4; bp++)
#pragma unroll
            for (int c = 0; c < 4; c++) {
                float2 q = un2(A[bp * 4 + c]);
                vals[bp * 2 + 0][c] = q.x;
                vals[bp * 2 + 1][c] = q.y;
            }
        if (!LOGITS) {
            float4 bb = make_float4(0.f, 0.f, 0.f, 0.f);
            if (bias) bb = *(const float4*)&bias[c4];
#pragma unroll
            for (int i = 0; i < 8; i++) {
                int b = b8 + i;
                *(float4*)&dstp[(size_t)b * dst_stride + c4] =
                    make_float4(vals[i][0] + bb.x, vals[i][1] + bb.y,
                                vals[i][2] + bb.z, vals[i][3] + bb.w);
            }
        } else {
#pragma unroll
            for (int i = 0; i < 8; i++) {
                int b = b8 + i;
#pragma unroll
                for (int c = 0; c < 4; c++) {
                    int col = col0 + c4 + c;
                    float v = -INFINITY;
                    if (col < Vc) {
                        v = vals[i][c] + bias[c4 + c];
                        dout[(size_t)b * Tc * Vc + (size_t)t * Vc + col] = v;
                    }
                    sl[b * 128 + c4 + c] = v;
                }
            }
        }
    }
    if (LOGITS) {
        __syncthreads();
        if (tid < 32) {
            int b = tid;
            float bv = -INFINITY; int bi = 0;
#pragma unroll 8
            for (int cq = 0; cq < 128; cq++) {
                float v = sl[b * 128 + cq];
                if (v > bv) { bv = v; bi = col0 + cq; }
            }
            g_pbv[tile * 32 + b] = bv;
            g_pbi[tile * 32 + b] = bi;
        }
    }
    __syncthreads();   // protect sw(red)/sl until every thread is done
}

// ---------------- init kernels ----------------
__global__ void k_mean(const float* __restrict__ feat, const float* __restrict__ emb) {
    int idx = blockIdx.x * blockDim.x + threadIdx.x;
    if (idx == 0) g_bar.v = 0u;
    if (idx < 16) g_cnt[idx] = 0u;
    if (idx < Bc * Ec) g_x[idx] = emb[(size_t)SOSc * Ec + (idx % Ec)];
    if (idx >= Bc * Fc) return;
    int b = idx / Fc, f = idx % Fc;
    float s = 0.f;
    const float* p = feat + (size_t)b * Nc * Fc + f;
#pragma unroll 8
    for (int n = 0; n < Nc; n++) s += p[(size_t)n * Fc];
    g_mean[idx] = s * (1.0f / 64.0f);
}

__global__ void k_h0c0(const float* __restrict__ Wh, const float* __restrict__ bh,
                       const float* __restrict__ Wc, const float* __restrict__ bc) {
    __shared__ __align__(16) float sm[64 * 36];
    int tid = threadIdx.x;
    int colg = blockIdx.x * 64 + (tid & 63);
    int bgrp = tid >> 6;
    float acc[8] = {0, 0, 0, 0, 0, 0, 0, 0};
    const float* W; float bias; float* dst;
    if (colg < Hc) { W = Wh + colg; bias = bh[colg]; dst = g_h[0] + colg; }
    else { W = Wc + (colg - Hc); bias = bc[colg - Hc]; dst = g_c[0] + (colg - Hc); }
    for (int kc = 0; kc < Fc; kc += 64) {
        __syncthreads();
        for (int e = tid; e < 2048; e += 256) {
            int kk = e >> 5, b = e & 31;
            sm[kk * 36 + b] = g_mean[b * Fc + kc + kk];
        }
        __syncthreads();
#pragma unroll 8
        for (int kk = 0; kk < 64; kk++) {
            float w = W[(size_t)(kc + kk) * Hc];
            const float* xr = &sm[kk * 36 + bgrp * 8];
#pragma unroll
            for (int i = 0; i < 8; i++) acc[i] = fmaf(xr[i], w, acc[i]);
        }
    }
#pragma unroll
    for (int i = 0; i < 8; i++) dst[(bgrp * 8 + i) * Hc] = acc[i] + bias;
}

__global__ void k_encproj(const float* __restrict__ feat, const float* __restrict__ W2,
                          const float* __restrict__ b2) {
    int tid = threadIdx.x;
    int rowbase = blockIdx.x * 64;
    int colbase = blockIdx.y * 64;
    int col = colbase + (tid & 63);
    int rgrp = tid >> 6;
    float acc[16];
#pragma unroll
    for (int i = 0; i < 16; i++) acc[i] = 0.f;
    __shared__ float As[64][33];
    __shared__ float Ws[32][65];
    for (int kc = 0; kc < Fc; kc += 32) {
        for (int e = tid; e < 64 * 32; e += 256) {
            int r = e >> 5, kk = e & 31;
            As[r][kk] = feat[(size_t)(rowbase + r) * Fc + kc + kk];
        }
        for (int e = tid; e < 32 * 64; e += 256) {
            int kk = e >> 6, c = e & 63;
            Ws[kk][c] = W2[(size_t)(kc + kk) * Hc + colbase + c];
        }
        __syncthreads();
#pragma unroll 8
        for (int kk = 0; kk < 32; kk++) {
            float w = Ws[kk][tid & 63];
#pragma unroll
            for (int i = 0; i < 16; i++) acc[i] += As[rgrp * 16 + i][kk] * w;
        }
        __syncthreads();
    }
    float bb = b2[col];
#pragma unroll
    for (int i = 0; i < 16; i++)
        g_encproj[(size_t)(rowbase + rgrp * 16 + i) * Hc + col] = acc[i] + bb;
}

// ---------------- persistent kernel ----------------
__global__ void __launch_bounds__(TPB, 1) k_persist(
    const float* __restrict__ feat, const float* __restrict__ emb,
    const float* __restrict__ W1, const float* __restrict__ b1,
    const float* __restrict__ Va, const float* __restrict__ bVa,
    const float* __restrict__ Wg, const float* __restrict__ bg,
    const float* __restrict__ Wx, const float* __restrict__ Whh,
    const float* __restrict__ blstm, const float* __restrict__ Wout,
    const float* __restrict__ bout, float* __restrict__ dout)
{
    extern __shared__ __align__(16) float dsm[];
    float* sw   = dsm;                            // 16384
    float* sb   = dsm + 16384;                    // 4608
    float* sl   = sb + 4608;                      // 4096
    float* sred = sl + 4096;                      // 512
    int*  sredi = (int*)(sred + 512);             // 512
    float* s_aux = (float*)(sredi + 512);         // 8

    const int bid = blockIdx.x;
    const int tid = threadIdx.x;

    // ===== pre-loop: hq(0)/glin(0)/gates-h(0) from h(0) =====
    if (bid < 30) {
        int u = bid;
        if (u < 4) {
            int col0 = u * 128;
            unit_fk<4, 0, false, 0>(sw, sb, sl, W1, Hc, 0, col0, Hc, g_h[0], b1 + col0,
                                    g_hq + col0, Hc, nullptr, 0, 0, tid);
        } else if (u < 14) {
            int col0 = (u - 4) * 128;
            unit_fk<4, 0, false, 0>(sw, sb, sl, Wg, Fc, 0, col0, Fc, g_h[0], bg + col0,
                                    g_glin + col0, Fc, nullptr, 0, 0, tid);
        } else {
            int col0 = (u - 14) * 128;
            unit_fk<4, 0, false, 0>(sw, sb, sl, Whh, G4, 0, col0, G4, g_h[0], nullptr,
                                    g_gh + col0, G4, nullptr, 0, 0, tid);
        }
    }
    gridbar();

    for (int t = 0; t < Tc; t++) {
        const int rp = t & 1, wp = rp ^ 1;

        // ===== PHASE A: attention (0..127) || argmax(t-1)->x (128..147) =====
        if (bid < 128) {
            int b = bid >> 2, sub = bid & 3;
            sl[tid] = __ldcg(&g_hq[b * Hc + tid]);   // Hc == TPB, bias included
            __syncthreads();
            int warp = tid >> 5, lane = tid & 31;
#pragma unroll
            for (int ni = 0; ni < 4; ni++) {
                int n = warp + ni * 16;
                const float* ep = g_encproj + (size_t)(b * Nc + n) * Hc;
                float acc = 0.f;
#pragma unroll 4
                for (int k = lane; k < Hc; k += 32) {
                    float v = sl[k] + ep[k];
                    acc = fmaf(fmaxf(v, 0.f), Va[k], acc);
                }
#pragma unroll
                for (int o = 16; o; o >>= 1) acc += __shfl_down_sync(0xffffffffu, acc, o);
                if (lane == 0) sred[n] = acc + bVa[0];
            }
            __syncthreads();
            if (tid < 64) {
                float m = sred[tid];
#pragma unroll
                for (int o = 16; o; o >>= 1) m = fmaxf(m, __shfl_xor_sync(0xffffffffu, m, o));
                if (lane == 0) s_aux[tid >> 5] = m;
            }
            __syncthreads();
            if (tid < 64) {
                float M = fmaxf(s_aux[0], s_aux[1]);
                float e = expf(sred[tid] - M);
                sred[tid] = e;
                float ss = e;
#pragma unroll
                for (int o = 16; o; o >>= 1) ss += __shfl_xor_sync(0xffffffffu, ss, o);
                if (lane == 0) s_aux[2 + (tid >> 5)] = ss;
            }
            __syncthreads();
            if (tid < 64) {
                float wv = sred[tid] / (s_aux[2] + s_aux[3]);
                sred[tid] = wv;
                if (sub == 0)
                    dout[AOFF + (size_t)b * Tc * Nc + (size_t)t * Nc + tid] = wv;
            }
            __syncthreads();
            if (tid < 320) {
                int f = sub * 320 + tid;
                const float* fb = feat + (size_t)b * Nc * Fc + f;
                float acc = 0.f;
#pragma unroll 8
                for (int n = 0; n < 64; n++) acc = fmaf(fb[(size_t)n * Fc], sred[n], acc);
                float gl = __ldcg(&g_glin[b * Fc + f]);
                g_ctx[b * Fc + f] = acc * sigf(gl);
            }
        } else if (t > 0) {
            int i = bid - 128;
            int half = tid >> 8, lt2 = tid & 255;
            int b = (i < 12) ? (2 * i + half) : (24 + (i - 12));
            bool active = (i < 12) || (half == 0);
            float bv = -INFINITY; int bi2 = 0x7fffffff;
            if (active && lt2 < NT79) {
                bv = __ldcg(&g_pbv[lt2 * 32 + b]);
                bi2 = __ldcg(&g_pbi[lt2 * 32 + b]);
            }
            sred[tid] = bv; sredi[tid] = bi2;
            __syncthreads();
            for (int o = 128; o; o >>= 1) {
                if (lt2 < o) {
                    if (sred[tid + o] > sred[tid] ||
                        (sred[tid + o] == sred[tid] && sredi[tid + o] < sredi[tid])) {
                        sred[tid] = sred[tid + o];
                        sredi[tid] = sredi[tid + o];
                    }
                }
                __syncthreads();
            }
            if (active) {
                int best = sredi[half * 256];
                for (int e = lt2; e < Ec; e += 256)
                    g_x[b * Ec + e] = emb[(size_t)best * Ec + e];
            }
        }
        gridbar();

        // ===== PHASE C(+D): gates x/ctx, j-grouped STRIP tiles: 16 x 7 Ksplits.
        // 7th finishing block per tile runs the LSTM pointwise for its 32 j inline.
        if (bid < 112) {
            int tile = bid / 7, kch = bid % 7;
            unit_fk<2, 1, false, 1>(sw, sb, sl, Wx, G4, kch * 256, tile * 32, G4,
                                    nullptr, nullptr, g_gp[kch] + tile * 128, G4,
                                    nullptr, 0, 0, tid);
            // completion counter (release: stores -> bar -> fence -> atomic)
            if (tid == 0) {
                __threadfence();
                sredi[0] = (int)atomicAdd(&g_cnt[tile], 1u);
            }
            __syncthreads();
            if (sredi[0] == 6) {
                __threadfence();   // acquire: make peers' partials visible
                if (tid == 0) g_cnt[tile] = 0u;
#pragma unroll
                for (int e = tid; e < 1024; e += TPB) {
                    int b = e >> 5, jj = e & 31;
                    int j = tile * 32 + jj;
                    const float* ghb = g_gh + (size_t)b * G4;
                    float gi = blstm[j]        + __ldcg(&ghb[j]);
                    float gf = blstm[512 + j]  + __ldcg(&ghb[512 + j]);
                    float gg = blstm[1024 + j] + __ldcg(&ghb[1024 + j]);
                    float go = blstm[1536 + j] + __ldcg(&ghb[1536 + j]);
#pragma unroll
                    for (int p = 0; p < 7; p++) {
                        const float* gp = g_gp[p] + (size_t)b * G4 + tile * 128;
                        gi += __ldcg(&gp[jj]);
                        gf += __ldcg(&gp[32 + jj]);
                        gg += __ldcg(&gp[64 + jj]);
                        go += __ldcg(&gp[96 + jj]);
                    }
                    float cprev = g_c[rp][b * Hc + j];
                    float iv = sigf(gi), fv = sigf(gf), gv = tanhf(gg), ov = sigf(go);
                    float c2 = fv * cprev + iv * gv;
                    float h2 = ov * tanhf(c2);
                    g_c[wp][b * Hc + j] = c2;
                    g_h[wp][b * Hc + j] = h2;
                    if (t == Tc - 1) {
                        dout[HOFF + b * Hc + j] = h2;
                        dout[COFF + b * Hc + j] = c2;
                    }
                }
            }
        }
        gridbar();

        // ===== PHASE E: logits(t) [79 tiles] || hq/glin/gates-h(t+1) [30 units] =====
        if (bid < NT79) {
            unit_fk<4, 0, true, 0>(sw, sb, sl, Wout, Vc, 0, bid * 128, Vc, g_h[wp],
                                   bout + bid * 128, nullptr, 0, dout, t, bid, tid);
        } else if (bid < 109) {
            int u = bid - NT79;
            if (u < 4) {
                int col0 = u * 128;
                unit_fk<4, 0, false, 0>(sw, sb, sl, W1, Hc, 0, col0, Hc, g_h[wp], b1 + col0,
                                        g_hq + col0, Hc, nullptr, 0, 0, tid);
            } else if (u < 14) {
                int col0 = (u - 4) * 128;
                unit_fk<4, 0, false, 0>(sw, sb, sl, Wg, Fc, 0, col0, Fc, g_h[wp], bg + col0,
                                        g_glin + col0, Fc, nullptr, 0, 0, tid);
            } else {
                int col0 = (u - 14) * 128;
                unit_fk<4, 0, false, 0>(sw, sb, sl, Whh, G4, 0, col0, G4, g_h[wp], nullptr,
                                        g_gh + col0, G4, nullptr, 0, 0, tid);
            }
        }
        gridbar();
    }
}

// ---------------- launcher ----------------
extern "C" void kernel_launch(void* const* d_in, const int* in_sizes, int n_in,
                              void* d_out, int out_size) {
    int off = (n_in > 2 && in_sizes[2] == 1) ? 1 : 0;
    const float* feat  = (const float*)d_in[0];
    const float* emb   = (const float*)d_in[2 + off];
    const float* W1    = (const float*)d_in[3 + off];
    const float* b1    = (const float*)d_in[4 + off];
    const float* W2    = (const float*)d_in[5 + off];
    const float* b2    = (const float*)d_in[6 + off];
    const float* Va    = (const float*)d_in[7 + off];
    const float* bVa   = (const float*)d_in[8 + off];
    const float* Wh    = (const float*)d_in[9 + off];
    const float* bh    = (const float*)d_in[10 + off];
    const float* Wc    = (const float*)d_in[11 + off];
    const float* bc    = (const float*)d_in[12 + off];
    const float* Wg    = (const float*)d_in[13 + off];
    const float* bg    = (const float*)d_in[14 + off];
    const float* Wx    = (const float*)d_in[15 + off];
    const float* Whh   = (const float*)d_in[16 + off];
    const float* blstm = (const float*)d_in[17 + off];
    const float* Wout  = (const float*)d_in[18 + off];
    const float* bout  = (const float*)d_in[19 + off];
    float* out = (float*)d_out;

    cudaFuncSetAttribute(k_persist, cudaFuncAttributeMaxDynamicSharedMemorySize, SMEM_BYTES);

    k_mean<<<160, 256>>>(feat, emb);
    k_h0c0<<<16, 256>>>(Wh, bh, Wc, bc);
    k_encproj<<<dim3(32, 8), 256>>>(feat, W2, b2);
    k_persist<<<NBLK, TPB, SMEM_BYTES>>>(feat, emb, W1, b1, Va, bVa, Wg, bg,
                                         Wx, Whh, blstm, Wout, bout, out);
}